// round 10
// baseline (speedup 1.0000x reference)
#include <cuda_runtime.h>
#include <math.h>

#define D_DIM 182
#define H_DIM 218
#define W_DIM 182
#define EMBED_DIM 768
#define REGION_MAX 116

#define TPB 256                     // 8 warps = 8 points per block
#define WPB (TPB / 32)

// first PERSIST_PTS output rows (96 MB) pinned dirty in L2 via evict_last
#define PERSIST_PTS 32768

__device__ __forceinline__ unsigned long long pk(float x, float y) {
    return (unsigned long long)__float_as_uint(x) |
           ((unsigned long long)__float_as_uint(y) << 32);
}
// 32-byte stores with L2 eviction hints (sm_103a: hinted st requires .v4.b64)
__device__ __forceinline__ void st32_last(void* p, float4 a, float4 b) {
    asm volatile("st.global.L2::evict_last.v4.b64 [%0], {%1,%2,%3,%4};"
                 :: "l"(p), "l"(pk(a.x, a.y)), "l"(pk(a.z, a.w)),
                    "l"(pk(b.x, b.y)), "l"(pk(b.z, b.w)) : "memory");
}
__device__ __forceinline__ void st32_first(void* p, float4 a, float4 b) {
    asm volatile("st.global.L2::evict_first.v4.b64 [%0], {%1,%2,%3,%4};"
                 :: "l"(p), "l"(pk(a.x, a.y)), "l"(pk(a.z, a.w)),
                    "l"(pk(b.x, b.y)), "l"(pk(b.z, b.w)) : "memory");
}

__global__ __launch_bounds__(TPB) void fused_kernel(
    const float* __restrict__ centers,
    const float* __restrict__ mri,
    const float* __restrict__ aal,
    const float* __restrict__ aal_data,
    const float* __restrict__ table,
    float* __restrict__ out,
    int total)
{
    __shared__ float sM[12];
    const int tid = threadIdx.x;

    if (tid == 0) {
        // invert aal (4x4 Gauss-Jordan, partial pivot), fuse with mri
        float a[4][8];
        #pragma unroll
        for (int i = 0; i < 4; i++)
            #pragma unroll
            for (int j = 0; j < 4; j++) {
                a[i][j] = aal[i * 4 + j];
                a[i][j + 4] = (i == j) ? 1.0f : 0.0f;
            }
        #pragma unroll
        for (int c = 0; c < 4; c++) {
            int p = c;
            float best = fabsf(a[c][c]);
            for (int r = c + 1; r < 4; r++) {
                float v = fabsf(a[r][c]);
                if (v > best) { best = v; p = r; }
            }
            if (p != c)
                for (int j = 0; j < 8; j++) { float t = a[c][j]; a[c][j] = a[p][j]; a[p][j] = t; }
            float inv = 1.0f / a[c][c];
            for (int j = 0; j < 8; j++) a[c][j] *= inv;
            for (int r = 0; r < 4; r++) {
                if (r == c) continue;
                float f = a[r][c];
                for (int j = 0; j < 8; j++) a[r][j] -= f * a[c][j];
            }
        }
        #pragma unroll
        for (int i = 0; i < 3; i++)
            #pragma unroll
            for (int j = 0; j < 4; j++) {
                float s = 0.0f;
                #pragma unroll
                for (int k = 0; k < 4; k++) s += a[i][k + 4] * mri[k * 4 + j];
                sM[i * 4 + j] = s;
            }
    }
    __syncthreads();

    // one warp per point
    const int warp = tid >> 5;
    const int lane = tid & 31;
    const int pt = blockIdx.x * WPB + warp;
    if (pt >= total) return;

    int region = 0;
    if (lane == 0) {
        float x0 = centers[pt * 3 + 0];
        float y0 = centers[pt * 3 + 1];
        float z0 = centers[pt * 3 + 2];
        float X = sM[0] * x0 + sM[1] * y0 + sM[2]  * z0 + sM[3];
        float Y = sM[4] * x0 + sM[5] * y0 + sM[6]  * z0 + sM[7];
        float Z = sM[8] * x0 + sM[9] * y0 + sM[10] * z0 + sM[11];
        int xi = (int)rintf(X);   // round-half-even, matches jnp.round
        int yi = (int)rintf(Y);
        int zi = (int)rintf(Z);
        bool inb = (xi >= 0) & (xi < D_DIM) & (yi >= 0) & (yi < H_DIM) &
                   (zi >= 0) & (zi < W_DIM);
        int cx = min(max(xi, 0), D_DIM - 1);
        int cy = min(max(yi, 0), H_DIM - 1);
        int cz = min(max(zi, 0), W_DIM - 1);
        int r = (int)__ldg(&aal_data[((size_t)cx * H_DIM + cy) * W_DIM + cz]);
        region = (inb && r >= 0 && r <= REGION_MAX) ? r : 0;
    }
    region = __shfl_sync(0xffffffffu, region, 0);

    // copy row: each lane owns 32B chunks (2 float4), 3 chunks per lane.
    const float4* __restrict__ src = (const float4*)(table + (size_t)region * EMBED_DIM);
    float4 a0 = __ldg(&src[2 * lane]);       float4 b0 = __ldg(&src[2 * lane + 1]);
    float4 a1 = __ldg(&src[2 * lane + 64]);  float4 b1 = __ldg(&src[2 * lane + 65]);
    float4 a2 = __ldg(&src[2 * lane + 128]); float4 b2 = __ldg(&src[2 * lane + 129]);

    float4* dst = (float4*)(out + (size_t)pt * EMBED_DIM);
    if (pt < PERSIST_PTS) {
        st32_last(dst + 2 * lane,       a0, b0);
        st32_last(dst + 2 * lane + 64,  a1, b1);
        st32_last(dst + 2 * lane + 128, a2, b2);
    } else {
        st32_first(dst + 2 * lane,       a0, b0);
        st32_first(dst + 2 * lane + 64,  a1, b1);
        st32_first(dst + 2 * lane + 128, a2, b2);
    }
}

extern "C" void kernel_launch(void* const* d_in, const int* in_sizes, int n_in,
                              void* d_out, int out_size) {
    const float* centers = (const float*)d_in[0];
    const float* mri     = (const float*)d_in[1];
    const float* aal     = (const float*)d_in[2];
    const float* atlas   = (const float*)d_in[3];
    const float* table   = (const float*)d_in[4];
    float* out = (float*)d_out;

    int total = in_sizes[0] / 3;
    int blocks = (total + WPB - 1) / WPB;

    fused_kernel<<<blocks, TPB>>>(centers, mri, aal, atlas, table, out, total);
}

// round 11
// speedup vs baseline: 1.1698x; 1.1698x over previous
#include <cuda_runtime.h>
#include <math.h>

#define D_DIM 182
#define H_DIM 218
#define W_DIM 182
#define EMBED_DIM 768
#define REGION_MAX 116

#define TPB 256
#define WPB (TPB / 32)           // 8 points per block

// first PERSIST_PTS output rows (~84 MB) pinned dirty in L2 via evict_last;
// leaves headroom for the 28 MB atlas + table in the 126 MB L2.
#define PERSIST_PTS 28672

__device__ float g_M[12];        // rows 0..2 of inv(aal)*mri

// ---- prep: invert aal (4x4 Gauss-Jordan, partial pivot), fuse with mri
__global__ void prep_kernel(const float* __restrict__ mri, const float* __restrict__ aal) {
    if (threadIdx.x != 0) return;
    float a[4][8];
    for (int i = 0; i < 4; i++)
        for (int j = 0; j < 4; j++) {
            a[i][j] = aal[i * 4 + j];
            a[i][j + 4] = (i == j) ? 1.0f : 0.0f;
        }
    for (int c = 0; c < 4; c++) {
        int p = c;
        float best = fabsf(a[c][c]);
        for (int r = c + 1; r < 4; r++) {
            float v = fabsf(a[r][c]);
            if (v > best) { best = v; p = r; }
        }
        if (p != c)
            for (int j = 0; j < 8; j++) { float t = a[c][j]; a[c][j] = a[p][j]; a[p][j] = t; }
        float inv = 1.0f / a[c][c];
        for (int j = 0; j < 8; j++) a[c][j] *= inv;
        for (int r = 0; r < 4; r++) {
            if (r == c) continue;
            float f = a[r][c];
            for (int j = 0; j < 8; j++) a[r][j] -= f * a[c][j];
        }
    }
    for (int i = 0; i < 3; i++)
        for (int j = 0; j < 4; j++) {
            float s = 0.0f;
            for (int k = 0; k < 4; k++) s += a[i][k + 4] * mri[k * 4 + j];
            g_M[i * 4 + j] = s;
        }
}

__device__ __forceinline__ unsigned long long pk(float x, float y) {
    return (unsigned long long)__float_as_uint(x) |
           ((unsigned long long)__float_as_uint(y) << 32);
}
// 32-byte stores with L2 eviction hints (sm_103a: hinted st requires .v4.b64)
__device__ __forceinline__ void st32_last(void* p, float4 a, float4 b) {
    asm volatile("st.global.L2::evict_last.v4.b64 [%0], {%1,%2,%3,%4};"
                 :: "l"(p), "l"(pk(a.x, a.y)), "l"(pk(a.z, a.w)),
                    "l"(pk(b.x, b.y)), "l"(pk(b.z, b.w)) : "memory");
}
__device__ __forceinline__ void st32_first(void* p, float4 a, float4 b) {
    asm volatile("st.global.L2::evict_first.v4.b64 [%0], {%1,%2,%3,%4};"
                 :: "l"(p), "l"(pk(a.x, a.y)), "l"(pk(a.z, a.w)),
                    "l"(pk(b.x, b.y)), "l"(pk(b.z, b.w)) : "memory");
}

// ---- main: one warp per point (R1 structure, hinted stores)
__global__ __launch_bounds__(TPB, 6) void embed_kernel(
    const float* __restrict__ centers,   // [total, 3]
    const float* __restrict__ aal_data,  // [D,H,W]
    const float* __restrict__ table,     // [117, 768]
    float* __restrict__ out,             // [total, 768]
    int total)
{
    const int warp = threadIdx.x >> 5;
    const int lane = threadIdx.x & 31;
    const int pt = blockIdx.x * WPB + warp;
    if (pt >= total) return;

    int region = 0;
    if (lane == 0) {
        float x0 = centers[pt * 3 + 0];
        float y0 = centers[pt * 3 + 1];
        float z0 = centers[pt * 3 + 2];
        float X = g_M[0] * x0 + g_M[1] * y0 + g_M[2]  * z0 + g_M[3];
        float Y = g_M[4] * x0 + g_M[5] * y0 + g_M[6]  * z0 + g_M[7];
        float Z = g_M[8] * x0 + g_M[9] * y0 + g_M[10] * z0 + g_M[11];
        int xi = (int)rintf(X);   // round-half-even, matches jnp.round
        int yi = (int)rintf(Y);
        int zi = (int)rintf(Z);
        bool inb = (xi >= 0) & (xi < D_DIM) & (yi >= 0) & (yi < H_DIM) &
                   (zi >= 0) & (zi < W_DIM);
        int cx = min(max(xi, 0), D_DIM - 1);
        int cy = min(max(yi, 0), H_DIM - 1);
        int cz = min(max(zi, 0), W_DIM - 1);
        int r = (int)__ldg(&aal_data[((size_t)cx * H_DIM + cy) * W_DIM + cz]);
        region = (inb && r >= 0 && r <= REGION_MAX) ? r : 0;
    }
    region = __shfl_sync(0xffffffffu, region, 0);

    // row copy: each lane owns three 32B chunks (2 float4 each)
    const float4* __restrict__ src = (const float4*)(table + (size_t)region * EMBED_DIM);
    float4 a0 = __ldg(&src[2 * lane]);       float4 b0 = __ldg(&src[2 * lane + 1]);
    float4 a1 = __ldg(&src[2 * lane + 64]);  float4 b1 = __ldg(&src[2 * lane + 65]);
    float4 a2 = __ldg(&src[2 * lane + 128]); float4 b2 = __ldg(&src[2 * lane + 129]);

    float4* dst = (float4*)(out + (size_t)pt * EMBED_DIM);
    if (pt < PERSIST_PTS) {
        st32_last(dst + 2 * lane,       a0, b0);
        st32_last(dst + 2 * lane + 64,  a1, b1);
        st32_last(dst + 2 * lane + 128, a2, b2);
    } else {
        st32_first(dst + 2 * lane,       a0, b0);
        st32_first(dst + 2 * lane + 64,  a1, b1);
        st32_first(dst + 2 * lane + 128, a2, b2);
    }
}

extern "C" void kernel_launch(void* const* d_in, const int* in_sizes, int n_in,
                              void* d_out, int out_size) {
    const float* centers = (const float*)d_in[0];
    const float* mri     = (const float*)d_in[1];
    const float* aal     = (const float*)d_in[2];
    const float* atlas   = (const float*)d_in[3];
    const float* table   = (const float*)d_in[4];
    float* out = (float*)d_out;

    int total = in_sizes[0] / 3;

    prep_kernel<<<1, 32>>>(mri, aal);

    int blocks = (total + WPB - 1) / WPB;
    embed_kernel<<<blocks, TPB>>>(centers, atlas, table, out, total);
}